// round 12
// baseline (speedup 1.0000x reference)
// LiteDACA v9 — v8 + k_conv_part smem reads vectorized (LDS.128 row quads +
// padded vectorized weights): 27 -> 12 LDS issues per ic. k_conv_part was
// smem-issue-bound (L1 53%, issue 50%).
#include <cuda_runtime.h>
#include <cuda_bf16.h>
#include <math.h>
#include <stdint.h>

// ---------------- problem constants ----------------
#define BATCH 8
#define CH    256
#define SCC   256
#define HWP   4096
#define HEADS 2
#define NPTS  4
#define TEMB  1024
#define NIMG  (BATCH*CH*HWP)
#define NOFF  (BATCH*2*HEADS*HWP)
#define PADK  40
#define CSPLIT 8
#define ICB   16

// ---------------- scratch ----------------
__device__ __nv_bfloat16 g_spb[BATCH*HWP*CH];
__device__ __nv_bfloat16 g_hvb[BATCH*HWP*HEADS*CH];
__device__ float g_part[CSPLIT][BATCH*6*HWP];
__device__ float g_off [BATCH*2*HEADS*HWP];
__device__ float g_attn[BATCH*HEADS*HWP];
__device__ float g_alpha[BATCH];
__device__ float g_losspart[128];

__device__ __forceinline__ float sigmoidf_(float x) { return 1.0f / (1.0f + expf(-x)); }

// ---------------- tensor-core helpers ----------------
__device__ __forceinline__ void ldsm_x4(uint32_t& r0, uint32_t& r1, uint32_t& r2, uint32_t& r3, uint32_t a) {
    asm volatile("ldmatrix.sync.aligned.m8n8.x4.shared.b16 {%0,%1,%2,%3}, [%4];"
                 : "=r"(r0), "=r"(r1), "=r"(r2), "=r"(r3) : "r"(a));
}
__device__ __forceinline__ void ldsm_x2(uint32_t& r0, uint32_t& r1, uint32_t a) {
    asm volatile("ldmatrix.sync.aligned.m8n8.x2.shared.b16 {%0,%1}, [%2];"
                 : "=r"(r0), "=r"(r1) : "r"(a));
}
__device__ __forceinline__ void mma16816(float c[4], const uint32_t a[4], const uint32_t b[2]) {
    asm volatile("mma.sync.aligned.m16n8k16.row.col.f32.bf16.bf16.f32 "
                 "{%0,%1,%2,%3}, {%4,%5,%6,%7}, {%8,%9}, {%0,%1,%2,%3};"
                 : "+f"(c[0]), "+f"(c[1]), "+f"(c[2]), "+f"(c[3])
                 : "r"(a[0]), "r"(a[1]), "r"(a[2]), "r"(a[3]), "r"(b[0]), "r"(b[1]));
}
__device__ __forceinline__ uint32_t smem_u32(const void* p) {
    return (uint32_t)__cvta_generic_to_shared(p);
}

// ---------------- gate ----------------
__global__ __launch_bounds__(256) void k_gate(const float* __restrict__ temb,
                                              const float* __restrict__ tw,
                                              const float* __restrict__ tb, int boff) {
    __shared__ float red[256];
    int b = blockIdx.x + boff, t = threadIdx.x;
    float s = 0.0f;
    for (int i = t; i < TEMB; i += 256) {
        float v = temb[b * TEMB + i];
        s += (v * sigmoidf_(v)) * tw[i];
    }
    red[t] = s;
    __syncthreads();
    for (int off = 128; off > 0; off >>= 1) {
        if (t < off) red[t] += red[t + off];
        __syncthreads();
    }
    if (t == 0) g_alpha[b] = sigmoidf_(red[0] + tb[0]);
}

// ---------------- style 1x1 conv: pipelined bf16 TC GEMM ----------------
__global__ __launch_bounds__(256) void k_style_gemm(const float* __restrict__ A,
                                                    const float* __restrict__ Wt,
                                                    const float* __restrict__ bias) {
    __shared__ __align__(16) __nv_bfloat16 As[2][128][PADK];
    __shared__ __align__(16) __nv_bfloat16 Bs[2][128][PADK];
    int b  = blockIdx.z;
    int p0 = blockIdx.x * 128, o0 = blockIdx.y * 128;
    const float* Ab = A + (size_t)b * SCC * HWP;
    int tid = threadIdx.x, lane = tid & 31, warp = tid >> 5;
    int wm = warp >> 2, wn = warp & 3;
    float acc[4][4][4];
#pragma unroll
    for (int mi = 0; mi < 4; mi++)
#pragma unroll
        for (int ni = 0; ni < 4; ni++)
#pragma unroll
            for (int q = 0; q < 4; q++) acc[mi][ni][q] = 0.0f;

    __nv_bfloat162 sA[8], sB[8];
#pragma unroll
    for (int j = 0; j < 8; j++) {
        int l = tid + j * 256;
        int pix = l & 127, kk2 = l >> 7;
        float v0 = Ab[(size_t)(2 * kk2) * HWP + p0 + pix];
        float v1 = Ab[(size_t)(2 * kk2 + 1) * HWP + p0 + pix];
        sA[j] = __floats2bfloat162_rn(v0, v1);
        float2 v = *(const float2*)&Wt[(size_t)(o0 + (l >> 4)) * SCC + 2 * (l & 15)];
        sB[j] = __floats2bfloat162_rn(v.x, v.y);
    }
#pragma unroll
    for (int j = 0; j < 8; j++) {
        int l = tid + j * 256;
        *(__nv_bfloat162*)&As[0][l & 127][2 * (l >> 7)] = sA[j];
        *(__nv_bfloat162*)&Bs[0][l >> 4][2 * (l & 15)]  = sB[j];
    }
    __syncthreads();

#pragma unroll
    for (int it = 0; it < 8; it++) {
        int cur = it & 1;
        if (it < 7) {
            int k0 = (it + 1) * 32;
#pragma unroll
            for (int j = 0; j < 8; j++) {
                int l = tid + j * 256;
                int pix = l & 127, kk2 = l >> 7;
                float v0 = Ab[(size_t)(k0 + 2 * kk2) * HWP + p0 + pix];
                float v1 = Ab[(size_t)(k0 + 2 * kk2 + 1) * HWP + p0 + pix];
                sA[j] = __floats2bfloat162_rn(v0, v1);
                float2 v = *(const float2*)&Wt[(size_t)(o0 + (l >> 4)) * SCC + k0 + 2 * (l & 15)];
                sB[j] = __floats2bfloat162_rn(v.x, v.y);
            }
        }
#pragma unroll
        for (int ks = 0; ks < 32; ks += 16) {
            uint32_t af[4][4], bf[4][2];
#pragma unroll
            for (int mi = 0; mi < 4; mi++)
                ldsm_x4(af[mi][0], af[mi][1], af[mi][2], af[mi][3],
                        smem_u32(&As[cur][wm * 64 + mi * 16 + (lane & 15)][ks + (lane >> 4) * 8]));
#pragma unroll
            for (int ni = 0; ni < 4; ni++)
                ldsm_x2(bf[ni][0], bf[ni][1],
                        smem_u32(&Bs[cur][wn * 32 + ni * 8 + (lane & 7)][ks + ((lane >> 3) & 1) * 8]));
#pragma unroll
            for (int mi = 0; mi < 4; mi++)
#pragma unroll
                for (int ni = 0; ni < 4; ni++) mma16816(acc[mi][ni], af[mi], bf[ni]);
        }
        if (it < 7) {
#pragma unroll
            for (int j = 0; j < 8; j++) {
                int l = tid + j * 256;
                *(__nv_bfloat162*)&As[cur ^ 1][l & 127][2 * (l >> 7)] = sA[j];
                *(__nv_bfloat162*)&Bs[cur ^ 1][l >> 4][2 * (l & 15)]  = sB[j];
            }
        }
        __syncthreads();
    }
    __nv_bfloat16* Cb = g_spb + (size_t)b * HWP * CH;
#pragma unroll
    for (int mi = 0; mi < 4; mi++) {
        int m = p0 + wm * 64 + mi * 16 + (lane >> 2);
#pragma unroll
        for (int ni = 0; ni < 4; ni++) {
            int n = o0 + wn * 32 + ni * 8 + (lane & 3) * 2;
            float b0 = bias[n], b1 = bias[n + 1];
            *(__nv_bfloat162*)&Cb[(size_t)m * CH + n] =
                __floats2bfloat162_rn(acc[mi][ni][0] + b0, acc[mi][ni][1] + b1);
            *(__nv_bfloat162*)&Cb[(size_t)(m + 8) * CH + n] =
                __floats2bfloat162_rn(acc[mi][ni][2] + b0, acc[mi][ni][3] + b1);
        }
    }
}

// ---------------- 3x3 conv partials: 64 channels per block, vectorized LDS ----
// grid (32 y-pairs, CSPLIT, 8 b); block 192 = 16 x-quads * 6 oc * 2 rows.
__global__ __launch_bounds__(192) void k_conv_part(const float* __restrict__ res,
                                                   const float* __restrict__ sty,
                                                   const float* __restrict__ offw,
                                                   const float* __restrict__ attw) {
    __shared__ __align__(16) float in_s[ICB][4][64];   // 16KB
    __shared__ __align__(16) float w_s[6][ICB][12];    // 4.5KB (9 used, padded for LDS.128)
    int b  = blockIdx.z;
    int cs = blockIdx.y;
    int y0 = blockIdx.x * 2;
    int tid = threadIdx.x;
    int xq = tid % 16;
    int oc = (tid / 16) % 6;
    int ys = tid / 96;
    int x0 = xq * 4;
    float acc[4] = {0.0f, 0.0f, 0.0f, 0.0f};

    int cbeg = cs * (512 / CSPLIT);
    for (int c0 = cbeg; c0 < cbeg + 512 / CSPLIT; c0 += ICB) {
        for (int l = tid; l < ICB * 4 * 64; l += 192) {
            int ic = l >> 8;
            int r  = (l >> 6) & 3;
            int x  = l & 63;
            int yy = y0 - 1 + r;
            float v = 0.0f;
            if (yy >= 0 && yy < 64) {
                int gc = c0 + ic;
                const float* src = (gc < 256)
                    ? res + (((size_t)b * 256 + gc) * 64 + yy) * 64
                    : sty + (((size_t)b * 256 + (gc - 256)) * 64 + yy) * 64;
                v = src[x];
            }
            in_s[ic][r][x] = v;
        }
        for (int l = tid; l < 6 * ICB * 9; l += 192) {
            int o = l / (ICB * 9);
            int rem = l - o * (ICB * 9);
            int ic = rem / 9, k = rem - ic * 9;
            int gc = c0 + ic;
            w_s[o][ic][k] = (o < 4) ? offw[(o * 512 + gc) * 9 + k]
                                    : attw[((o - 4) * 512 + gc) * 9 + k];
        }
        __syncthreads();
#pragma unroll 4
        for (int ic = 0; ic < ICB; ic++) {
            // weights: 2x LDS.128 + 1 scalar (row pitch 48B, 16B-aligned)
            float4 wa = *(const float4*)&w_s[oc][ic][0];
            float4 wb = *(const float4*)&w_s[oc][ic][4];
            float  w8 = w_s[oc][ic][8];
            float wk[3][3] = {{wa.x, wa.y, wa.z},
                              {wa.w, wb.x, wb.y},
                              {wb.z, wb.w, w8}};
#pragma unroll
            for (int ky = 0; ky < 3; ky++) {
                const float* row = in_s[ic][ys + ky];
                float  iv0 = (x0 > 0)      ? row[x0 - 1] : 0.0f;
                float4 v   = *(const float4*)&row[x0];        // 16B-aligned
                float  iv5 = (x0 + 4 < 64) ? row[x0 + 4] : 0.0f;
                float w0 = wk[ky][0], w1 = wk[ky][1], w2 = wk[ky][2];
                acc[0] += iv0 * w0 + v.x * w1 + v.y * w2;
                acc[1] += v.x * w0 + v.y * w1 + v.z * w2;
                acc[2] += v.y * w0 + v.z * w1 + v.w * w2;
                acc[3] += v.z * w0 + v.w * w1 + iv5 * w2;
            }
        }
        __syncthreads();
    }
    int y = y0 + ys;
    float* dst = &g_part[cs][(((size_t)b * 6 + oc) * 64 + y) * 64 + x0];
#pragma unroll
    for (int d = 0; d < 4; d++) dst[d] = acc[d];
}

// ---------------- conv reduce ----------------
__global__ __launch_bounds__(256) void k_conv_reduce(const float* __restrict__ offb,
                                                     const float* __restrict__ attb) {
    int i = blockIdx.x * 256 + threadIdx.x;
    int pix = i & (HWP - 1);
    int t = i >> 12;
    int oc = t % 6, b = t / 6;
    float s = 0.0f;
#pragma unroll
    for (int cs = 0; cs < CSPLIT; cs++) s += g_part[cs][i];
    if (oc < 4)
        g_off[((size_t)b * 4 + oc) * HWP + pix] = s + offb[oc];
    else
        g_attn[((size_t)b * 2 + (oc - 4)) * HWP + pix] = sigmoidf_(s + attb[oc - 4]);
}

// ---------------- offset_loss ----------------
__global__ __launch_bounds__(256) void k_loss_part() {
    __shared__ float red[256];
    int t = threadIdx.x;
    int base = blockIdx.x * 1024;
    float s = 0.0f;
#pragma unroll
    for (int i = 0; i < 4; i++) s += fabsf(g_off[base + t + i * 256]);
    red[t] = s;
    __syncthreads();
    for (int off = 128; off > 0; off >>= 1) {
        if (t < off) red[t] += red[t + off];
        __syncthreads();
    }
    if (t == 0) g_losspart[blockIdx.x] = red[0];
}

__global__ __launch_bounds__(128) void k_loss_final(float* __restrict__ out, int out_size) {
    __shared__ float red[128];
    int t = threadIdx.x;
    red[t] = g_losspart[t];
    __syncthreads();
    for (int off = 64; off > 0; off >>= 1) {
        if (t < off) red[t] += red[t + off];
        __syncthreads();
    }
    if (t == 0 && out_size > NIMG) out[NIMG] = red[0] * (1.0f / (float)NOFF);
}

// ---------------- deformable sampling: 8ch/thread uint4 gathers ----------------
__global__ __launch_bounds__(256) void k_sample(const float* __restrict__ Wp,
                                                const float* __restrict__ bpts) {
    __shared__ int   s_idx[64][16];
    __shared__ float s_w[64][16];
    int y = blockIdx.x, head = blockIdx.y, b = blockIdx.z;
    int tid = threadIdx.x;
    {
        int x = tid >> 2, p = tid & 3;
        float off0 = g_off[((((size_t)b * 4) + (head * 2 + 0)) * 64 + y) * 64 + x];
        float off1 = g_off[((((size_t)b * 4) + (head * 2 + 1)) * 64 + y) * 64 + x];
        float av   = g_attn[((((size_t)b * 2) + head) * 64 + y) * 64 + x];
        float s = av * Wp[head * NPTS + p];
        float g0 = (-1.0f + (float)y * (2.0f / 63.0f)) + bpts[p * 2 + 0] + off0;
        float g1 = (-1.0f + (float)x * (2.0f / 63.0f)) + bpts[p * 2 + 1] + off1;
        float gx = (g0 + 1.0f) * 0.5f * 63.0f;
        float gy = (g1 + 1.0f) * 0.5f * 63.0f;
        float x0f = floorf(gx), y0f = floorf(gy);
        float wx1 = gx - x0f, wx0 = 1.0f - wx1;
        float wy1 = gy - y0f, wy0 = 1.0f - wy1;
        int x0 = (int)x0f, y0i = (int)y0f;
        int xs_[2] = {x0, x0 + 1};
        int ys_[2] = {y0i, y0i + 1};
        float wxv[2] = {wx0, wx1};
        float wyv[2] = {wy0, wy1};
#pragma unroll
        for (int ty2 = 0; ty2 < 2; ty2++)
#pragma unroll
            for (int tx2 = 0; tx2 < 2; tx2++) {
                int xi = xs_[tx2], yi = ys_[ty2];
                bool valid = (xi >= 0) && (xi <= 63) && (yi >= 0) && (yi <= 63);
                int t = ty2 * 2 + tx2;
                s_w[x][p * 4 + t]   = valid ? (wxv[tx2] * wyv[ty2] * s) : 0.0f;
                s_idx[x][p * 4 + t] = valid ? ((yi * 64 + xi) * CH) : 0;
            }
    }
    __syncthreads();
    int lane = tid & 31, warp = tid >> 5;
    const __nv_bfloat16* spb = g_spb + (size_t)b * HWP * CH + lane * 8;
    __nv_bfloat16* hvb = g_hvb + (size_t)b * HWP * (HEADS * CH) + head * CH + lane * 8;
#pragma unroll
    for (int xi = 0; xi < 8; xi++) {
        int x = warp * 8 + xi;
        float a0 = 0.f, a1 = 0.f, a2 = 0.f, a3 = 0.f, a4 = 0.f, a5 = 0.f, a6 = 0.f, a7 = 0.f;
#pragma unroll
        for (int t = 0; t < 16; t++) {
            float w = s_w[x][t];
            if (w != 0.0f) {
                uint4 v = *(const uint4*)(spb + s_idx[x][t]);
                a0 += w * __uint_as_float(v.x << 16);
                a1 += w * __uint_as_float(v.x & 0xFFFF0000u);
                a2 += w * __uint_as_float(v.y << 16);
                a3 += w * __uint_as_float(v.y & 0xFFFF0000u);
                a4 += w * __uint_as_float(v.z << 16);
                a5 += w * __uint_as_float(v.z & 0xFFFF0000u);
                a6 += w * __uint_as_float(v.w << 16);
                a7 += w * __uint_as_float(v.w & 0xFFFF0000u);
            }
        }
        __nv_bfloat162 p0 = __floats2bfloat162_rn(a0, a1);
        __nv_bfloat162 p1 = __floats2bfloat162_rn(a2, a3);
        __nv_bfloat162 p2 = __floats2bfloat162_rn(a4, a5);
        __nv_bfloat162 p3 = __floats2bfloat162_rn(a6, a7);
        uint4 o;
        o.x = *(uint32_t*)&p0; o.y = *(uint32_t*)&p1; o.z = *(uint32_t*)&p2; o.w = *(uint32_t*)&p3;
        *(uint4*)(hvb + (size_t)(y * 64 + x) * (HEADS * CH)) = o;
    }
}

// ---------------- fuse 1x1 conv: pipelined bf16 TC GEMM + blend ----------------
#define TILE_BYTES (128 * PADK * 2)
__global__ __launch_bounds__(256) void k_fuse_gemm(const float* __restrict__ Wt,
                                                   const float* __restrict__ bias,
                                                   const float* __restrict__ res,
                                                   float* __restrict__ out) {
    __shared__ __align__(16) char smraw[4 * TILE_BYTES];
    typedef __nv_bfloat16 (*TileP)[PADK];
    TileP Abuf[2] = { (TileP)(smraw),                  (TileP)(smraw + TILE_BYTES) };
    TileP Bbuf[2] = { (TileP)(smraw + 2 * TILE_BYTES), (TileP)(smraw + 3 * TILE_BYTES) };
    float (*Cs)[34] = (float(*)[34])smraw;

    int b  = blockIdx.z;
    int p0 = blockIdx.x * 128, o0 = blockIdx.y * 128;
    const __nv_bfloat16* Ab = g_hvb + (size_t)b * HWP * 512;
    int tid = threadIdx.x, lane = tid & 31, warp = tid >> 5;
    int wm = warp >> 2, wn = warp & 3;
    float acc[4][4][4];
#pragma unroll
    for (int mi = 0; mi < 4; mi++)
#pragma unroll
        for (int ni = 0; ni < 4; ni++)
#pragma unroll
            for (int q = 0; q < 4; q++) acc[mi][ni][q] = 0.0f;

    uint4 sA4[2];
    __nv_bfloat162 sB[8];
#pragma unroll
    for (int j = 0; j < 2; j++) {
        int l = tid + j * 256;
        sA4[j] = *(const uint4*)(Ab + (size_t)(p0 + (l >> 2)) * 512 + (l & 3) * 8);
    }
#pragma unroll
    for (int j = 0; j < 8; j++) {
        int l = tid + j * 256;
        float2 v = *(const float2*)&Wt[(size_t)(o0 + (l >> 4)) * 512 + 2 * (l & 15)];
        sB[j] = __floats2bfloat162_rn(v.x, v.y);
    }
#pragma unroll
    for (int j = 0; j < 2; j++) {
        int l = tid + j * 256;
        *(uint4*)&Abuf[0][l >> 2][(l & 3) * 8] = sA4[j];
    }
#pragma unroll
    for (int j = 0; j < 8; j++) {
        int l = tid + j * 256;
        *(__nv_bfloat162*)&Bbuf[0][l >> 4][2 * (l & 15)] = sB[j];
    }
    __syncthreads();

#pragma unroll
    for (int it = 0; it < 16; it++) {
        int cur = it & 1;
        if (it < 15) {
            int k0 = (it + 1) * 32;
#pragma unroll
            for (int j = 0; j < 2; j++) {
                int l = tid + j * 256;
                sA4[j] = *(const uint4*)(Ab + (size_t)(p0 + (l >> 2)) * 512 + k0 + (l & 3) * 8);
            }
#pragma unroll
            for (int j = 0; j < 8; j++) {
                int l = tid + j * 256;
                float2 v = *(const float2*)&Wt[(size_t)(o0 + (l >> 4)) * 512 + k0 + 2 * (l & 15)];
                sB[j] = __floats2bfloat162_rn(v.x, v.y);
            }
        }
#pragma unroll
        for (int ks = 0; ks < 32; ks += 16) {
            uint32_t af[4][4], bf[4][2];
#pragma unroll
            for (int mi = 0; mi < 4; mi++)
                ldsm_x4(af[mi][0], af[mi][1], af[mi][2], af[mi][3],
                        smem_u32(&Abuf[cur][wm * 64 + mi * 16 + (lane & 15)][ks + (lane >> 4) * 8]));
#pragma unroll
            for (int ni = 0; ni < 4; ni++)
                ldsm_x2(bf[ni][0], bf[ni][1],
                        smem_u32(&Bbuf[cur][wn * 32 + ni * 8 + (lane & 7)][ks + ((lane >> 3) & 1) * 8]));
#pragma unroll
            for (int mi = 0; mi < 4; mi++)
#pragma unroll
                for (int ni = 0; ni < 4; ni++) mma16816(acc[mi][ni], af[mi], bf[ni]);
        }
        if (it < 15) {
#pragma unroll
            for (int j = 0; j < 2; j++) {
                int l = tid + j * 256;
                *(uint4*)&Abuf[cur ^ 1][l >> 2][(l & 3) * 8] = sA4[j];
            }
#pragma unroll
            for (int j = 0; j < 8; j++) {
                int l = tid + j * 256;
                *(__nv_bfloat162*)&Bbuf[cur ^ 1][l >> 4][2 * (l & 15)] = sB[j];
            }
        }
        __syncthreads();
    }
    float al = g_alpha[b];
    for (int j = 0; j < 4; j++) {
        if (wn == j) {
#pragma unroll
            for (int mi = 0; mi < 4; mi++) {
                int m = wm * 64 + mi * 16 + (lane >> 2);
#pragma unroll
                for (int ni = 0; ni < 4; ni++) {
                    int nl = ni * 8 + (lane & 3) * 2;
                    *(float2*)&Cs[m][nl]     = make_float2(acc[mi][ni][0], acc[mi][ni][1]);
                    *(float2*)&Cs[m + 8][nl] = make_float2(acc[mi][ni][2], acc[mi][ni][3]);
                }
            }
        }
        __syncthreads();
        int pix = tid & 127, ob = tid >> 7;
#pragma unroll
        for (int oi = 0; oi < 16; oi++) {
            int ol = ob + oi * 2;
            int o = o0 + j * 32 + ol;
            float v = Cs[pix][ol] + bias[o];
            size_t gi = ((size_t)b * CH + o) * HWP + p0 + pix;
            out[gi] = al * v + (1.0f - al) * res[gi];
        }
        __syncthreads();
    }
}

// ---------------- launch (k_conv_part at index 3 for ncu) ----------------
extern "C" void kernel_launch(void* const* d_in, const int* in_sizes, int n_in,
                              void* d_out, int out_size) {
    const float* res    = (const float*)d_in[0];
    const float* sty    = (const float*)d_in[1];
    const float* temb   = (const float*)d_in[2];
    const float* spw    = (const float*)d_in[3];
    const float* spb    = (const float*)d_in[4];
    const float* offw   = (const float*)d_in[5];
    const float* offb   = (const float*)d_in[6];
    const float* attw   = (const float*)d_in[7];
    const float* attb   = (const float*)d_in[8];
    const float* Wp     = (const float*)d_in[9];
    const float* fw     = (const float*)d_in[10];
    const float* fb     = (const float*)d_in[11];
    const float* tgw    = (const float*)d_in[12];
    const float* tgb    = (const float*)d_in[13];
    const float* bpts   = (const float*)d_in[14];
    float* out = (float*)d_out;

    k_style_gemm<<<dim3(HWP / 128, CH / 128, BATCH), 256>>>(sty, spw, spb);      // 0
    k_gate<<<4, 256>>>(temb, tgw, tgb, 0);                                       // 1
    k_gate<<<4, 256>>>(temb, tgw, tgb, 4);                                       // 2
    k_conv_part<<<dim3(32, CSPLIT, BATCH), 192>>>(res, sty, offw, attw);         // 3 <- ncu slot
    k_conv_reduce<<<(BATCH * 6 * HWP) / 256, 256>>>(offb, attb);                 // 4
    k_sample<<<dim3(64, HEADS, BATCH), 256>>>(Wp, bpts);                         // 5
    k_loss_part<<<128, 256>>>();                                                 // 6
    k_loss_final<<<1, 128>>>(out, out_size);                                     // 7
    k_fuse_gemm<<<dim3(HWP / 128, CH / 128, BATCH), 256>>>(fw, fb, res, out);    // 8
}

// round 14
// speedup vs baseline: 1.1571x; 1.1571x over previous
// LiteDACA v10b — identical to v10; resubmission after infra failure (5th occurrence).
#include <cuda_runtime.h>
#include <cuda_bf16.h>
#include <math.h>
#include <stdint.h>

// ---------------- problem constants ----------------
#define BATCH 8
#define CH    256
#define SCC   256
#define HWP   4096
#define HEADS 2
#define NPTS  4
#define TEMB  1024
#define NIMG  (BATCH*CH*HWP)
#define NOFF  (BATCH*2*HEADS*HWP)
#define PADK  40
#define CSPLIT 16         // channel slices (32 ch each)
#define ICB   8           // channels per smem chunk

// ---------------- scratch ----------------
__device__ __nv_bfloat16 g_spb[BATCH*HWP*CH];
__device__ __nv_bfloat16 g_hvb[BATCH*HWP*HEADS*CH];
__device__ float g_part[CSPLIT][BATCH*6*HWP];   // 12.6 MB
__device__ float g_off [BATCH*2*HEADS*HWP];
__device__ float g_attn[BATCH*HEADS*HWP];
__device__ float g_alpha[BATCH];
__device__ float g_losspart[128];

__device__ __forceinline__ float sigmoidf_(float x) { return 1.0f / (1.0f + expf(-x)); }

// ---------------- tensor-core helpers ----------------
__device__ __forceinline__ void ldsm_x4(uint32_t& r0, uint32_t& r1, uint32_t& r2, uint32_t& r3, uint32_t a) {
    asm volatile("ldmatrix.sync.aligned.m8n8.x4.shared.b16 {%0,%1,%2,%3}, [%4];"
                 : "=r"(r0), "=r"(r1), "=r"(r2), "=r"(r3) : "r"(a));
}
__device__ __forceinline__ void ldsm_x2(uint32_t& r0, uint32_t& r1, uint32_t a) {
    asm volatile("ldmatrix.sync.aligned.m8n8.x2.shared.b16 {%0,%1}, [%2];"
                 : "=r"(r0), "=r"(r1) : "r"(a));
}
__device__ __forceinline__ void mma16816(float c[4], const uint32_t a[4], const uint32_t b[2]) {
    asm volatile("mma.sync.aligned.m16n8k16.row.col.f32.bf16.bf16.f32 "
                 "{%0,%1,%2,%3}, {%4,%5,%6,%7}, {%8,%9}, {%0,%1,%2,%3};"
                 : "+f"(c[0]), "+f"(c[1]), "+f"(c[2]), "+f"(c[3])
                 : "r"(a[0]), "r"(a[1]), "r"(a[2]), "r"(a[3]), "r"(b[0]), "r"(b[1]));
}
__device__ __forceinline__ uint32_t smem_u32(const void* p) {
    return (uint32_t)__cvta_generic_to_shared(p);
}

// ---------------- gate ----------------
__global__ __launch_bounds__(256) void k_gate(const float* __restrict__ temb,
                                              const float* __restrict__ tw,
                                              const float* __restrict__ tb, int boff) {
    __shared__ float red[256];
    int b = blockIdx.x + boff, t = threadIdx.x;
    float s = 0.0f;
    for (int i = t; i < TEMB; i += 256) {
        float v = temb[b * TEMB + i];
        s += (v * sigmoidf_(v)) * tw[i];
    }
    red[t] = s;
    __syncthreads();
    for (int off = 128; off > 0; off >>= 1) {
        if (t < off) red[t] += red[t + off];
        __syncthreads();
    }
    if (t == 0) g_alpha[b] = sigmoidf_(red[0] + tb[0]);
}

// ---------------- style 1x1 conv: pipelined bf16 TC GEMM ----------------
__global__ __launch_bounds__(256) void k_style_gemm(const float* __restrict__ A,
                                                    const float* __restrict__ Wt,
                                                    const float* __restrict__ bias) {
    __shared__ __align__(16) __nv_bfloat16 As[2][128][PADK];
    __shared__ __align__(16) __nv_bfloat16 Bs[2][128][PADK];
    int b  = blockIdx.z;
    int p0 = blockIdx.x * 128, o0 = blockIdx.y * 128;
    const float* Ab = A + (size_t)b * SCC * HWP;
    int tid = threadIdx.x, lane = tid & 31, warp = tid >> 5;
    int wm = warp >> 2, wn = warp & 3;
    float acc[4][4][4];
#pragma unroll
    for (int mi = 0; mi < 4; mi++)
#pragma unroll
        for (int ni = 0; ni < 4; ni++)
#pragma unroll
            for (int q = 0; q < 4; q++) acc[mi][ni][q] = 0.0f;

    __nv_bfloat162 sA[8], sB[8];
#pragma unroll
    for (int j = 0; j < 8; j++) {
        int l = tid + j * 256;
        int pix = l & 127, kk2 = l >> 7;
        float v0 = Ab[(size_t)(2 * kk2) * HWP + p0 + pix];
        float v1 = Ab[(size_t)(2 * kk2 + 1) * HWP + p0 + pix];
        sA[j] = __floats2bfloat162_rn(v0, v1);
        float2 v = *(const float2*)&Wt[(size_t)(o0 + (l >> 4)) * SCC + 2 * (l & 15)];
        sB[j] = __floats2bfloat162_rn(v.x, v.y);
    }
#pragma unroll
    for (int j = 0; j < 8; j++) {
        int l = tid + j * 256;
        *(__nv_bfloat162*)&As[0][l & 127][2 * (l >> 7)] = sA[j];
        *(__nv_bfloat162*)&Bs[0][l >> 4][2 * (l & 15)]  = sB[j];
    }
    __syncthreads();

#pragma unroll
    for (int it = 0; it < 8; it++) {
        int cur = it & 1;
        if (it < 7) {
            int k0 = (it + 1) * 32;
#pragma unroll
            for (int j = 0; j < 8; j++) {
                int l = tid + j * 256;
                int pix = l & 127, kk2 = l >> 7;
                float v0 = Ab[(size_t)(k0 + 2 * kk2) * HWP + p0 + pix];
                float v1 = Ab[(size_t)(k0 + 2 * kk2 + 1) * HWP + p0 + pix];
                sA[j] = __floats2bfloat162_rn(v0, v1);
                float2 v = *(const float2*)&Wt[(size_t)(o0 + (l >> 4)) * SCC + k0 + 2 * (l & 15)];
                sB[j] = __floats2bfloat162_rn(v.x, v.y);
            }
        }
#pragma unroll
        for (int ks = 0; ks < 32; ks += 16) {
            uint32_t af[4][4], bf[4][2];
#pragma unroll
            for (int mi = 0; mi < 4; mi++)
                ldsm_x4(af[mi][0], af[mi][1], af[mi][2], af[mi][3],
                        smem_u32(&As[cur][wm * 64 + mi * 16 + (lane & 15)][ks + (lane >> 4) * 8]));
#pragma unroll
            for (int ni = 0; ni < 4; ni++)
                ldsm_x2(bf[ni][0], bf[ni][1],
                        smem_u32(&Bs[cur][wn * 32 + ni * 8 + (lane & 7)][ks + ((lane >> 3) & 1) * 8]));
#pragma unroll
            for (int mi = 0; mi < 4; mi++)
#pragma unroll
                for (int ni = 0; ni < 4; ni++) mma16816(acc[mi][ni], af[mi], bf[ni]);
        }
        if (it < 7) {
#pragma unroll
            for (int j = 0; j < 8; j++) {
                int l = tid + j * 256;
                *(__nv_bfloat162*)&As[cur ^ 1][l & 127][2 * (l >> 7)] = sA[j];
                *(__nv_bfloat162*)&Bs[cur ^ 1][l >> 4][2 * (l & 15)]  = sB[j];
            }
        }
        __syncthreads();
    }
    __nv_bfloat16* Cb = g_spb + (size_t)b * HWP * CH;
#pragma unroll
    for (int mi = 0; mi < 4; mi++) {
        int m = p0 + wm * 64 + mi * 16 + (lane >> 2);
#pragma unroll
        for (int ni = 0; ni < 4; ni++) {
            int n = o0 + wn * 32 + ni * 8 + (lane & 3) * 2;
            float b0 = bias[n], b1 = bias[n + 1];
            *(__nv_bfloat162*)&Cb[(size_t)m * CH + n] =
                __floats2bfloat162_rn(acc[mi][ni][0] + b0, acc[mi][ni][1] + b1);
            *(__nv_bfloat162*)&Cb[(size_t)(m + 8) * CH + n] =
                __floats2bfloat162_rn(acc[mi][ni][2] + b0, acc[mi][ni][3] + b1);
        }
    }
}

// ---------------- 3x3 conv partials: 32ch/slice, all-6-oc per thread ----------
// grid (8 ygroups, CSPLIT, 8 b); block 128 = 16 x-quads * 8 rows.
__global__ __launch_bounds__(128) void k_conv_part(const float* __restrict__ res,
                                                   const float* __restrict__ sty,
                                                   const float* __restrict__ offw,
                                                   const float* __restrict__ attw) {
    __shared__ __align__(16) float in_s[ICB][10][64];  // 20KB: rows y0-1..y0+8
    __shared__ float w_s[ICB][6][12];                  // 2.3KB (9 used)
    int b  = blockIdx.z;
    int cs = blockIdx.y;
    int y0 = blockIdx.x * 8;
    int tid = threadIdx.x;
    int xq = tid & 15, yl = tid >> 4;   // yl 0..7
    int x0 = xq * 4;
    float acc[6][4];
#pragma unroll
    for (int o = 0; o < 6; o++)
#pragma unroll
        for (int d = 0; d < 4; d++) acc[o][d] = 0.0f;

    int cbeg = cs * 32;
    for (int c0 = cbeg; c0 < cbeg + 32; c0 += ICB) {
        for (int l = tid; l < ICB * 10 * 64; l += 128) {
            int ic  = l / 640;
            int rem = l - ic * 640;
            int r   = rem >> 6;
            int x   = rem & 63;
            int yy  = y0 - 1 + r;
            float v = 0.0f;
            if (yy >= 0 && yy < 64) {
                int gc = c0 + ic;
                const float* src = (gc < 256)
                    ? res + (((size_t)b * 256 + gc) * 64 + yy) * 64
                    : sty + (((size_t)b * 256 + (gc - 256)) * 64 + yy) * 64;
                v = src[x];
            }
            in_s[ic][r][x] = v;
        }
        for (int l = tid; l < ICB * 6 * 9; l += 128) {
            int ic  = l / 54;
            int rem = l - ic * 54;
            int o = rem / 9, k = rem - o * 9;
            int gc = c0 + ic;
            w_s[ic][o][k] = (o < 4) ? offw[(o * 512 + gc) * 9 + k]
                                    : attw[((o - 4) * 512 + gc) * 9 + k];
        }
        __syncthreads();
#pragma unroll 2
        for (int ic = 0; ic < ICB; ic++) {
#pragma unroll
            for (int ky = 0; ky < 3; ky++) {
                const float* row = in_s[ic][yl + ky];
                float  iv0 = (x0 > 0)      ? row[x0 - 1] : 0.0f;
                float4 v   = *(const float4*)&row[x0];
                float  iv5 = (x0 + 4 < 64) ? row[x0 + 4] : 0.0f;
#pragma unroll
                for (int o = 0; o < 6; o++) {
                    float w0 = w_s[ic][o][ky * 3 + 0];   // warp-uniform -> broadcast
                    float w1 = w_s[ic][o][ky * 3 + 1];
                    float w2 = w_s[ic][o][ky * 3 + 2];
                    acc[o][0] += iv0 * w0 + v.x * w1 + v.y * w2;
                    acc[o][1] += v.x * w0 + v.y * w1 + v.z * w2;
                    acc[o][2] += v.y * w0 + v.z * w1 + v.w * w2;
                    acc[o][3] += v.z * w0 + v.w * w1 + iv5 * w2;
                }
            }
        }
        __syncthreads();
    }
    int y = y0 + yl;
#pragma unroll
    for (int o = 0; o < 6; o++) {
        float4 vv = make_float4(acc[o][0], acc[o][1], acc[o][2], acc[o][3]);
        *(float4*)&g_part[cs][(((size_t)b * 6 + o) * 64 + y) * 64 + x0] = vv;
    }
}

// ---------------- conv reduce ----------------
__global__ __launch_bounds__(256) void k_conv_reduce(const float* __restrict__ offb,
                                                     const float* __restrict__ attb) {
    int i = blockIdx.x * 256 + threadIdx.x;
    int pix = i & (HWP - 1);
    int t = i >> 12;
    int oc = t % 6, b = t / 6;
    float s = 0.0f;
#pragma unroll
    for (int cs = 0; cs < CSPLIT; cs++) s += g_part[cs][i];
    if (oc < 4)
        g_off[((size_t)b * 4 + oc) * HWP + pix] = s + offb[oc];
    else
        g_attn[((size_t)b * 2 + (oc - 4)) * HWP + pix] = sigmoidf_(s + attb[oc - 4]);
}

// ---------------- offset_loss ----------------
__global__ __launch_bounds__(256) void k_loss_part() {
    __shared__ float red[256];
    int t = threadIdx.x;
    int base = blockIdx.x * 1024;
    float s = 0.0f;
#pragma unroll
    for (int i = 0; i < 4; i++) s += fabsf(g_off[base + t + i * 256]);
    red[t] = s;
    __syncthreads();
    for (int off = 128; off > 0; off >>= 1) {
        if (t < off) red[t] += red[t + off];
        __syncthreads();
    }
    if (t == 0) g_losspart[blockIdx.x] = red[0];
}

__global__ __launch_bounds__(128) void k_loss_final(float* __restrict__ out, int out_size) {
    __shared__ float red[128];
    int t = threadIdx.x;
    red[t] = g_losspart[t];
    __syncthreads();
    for (int off = 64; off > 0; off >>= 1) {
        if (t < off) red[t] += red[t + off];
        __syncthreads();
    }
    if (t == 0 && out_size > NIMG) out[NIMG] = red[0] * (1.0f / (float)NOFF);
}

// ---------------- deformable sampling: 8ch/thread uint4 gathers ----------------
__global__ __launch_bounds__(256) void k_sample(const float* __restrict__ Wp,
                                                const float* __restrict__ bpts) {
    __shared__ int   s_idx[64][16];
    __shared__ float s_w[64][16];
    int y = blockIdx.x, head = blockIdx.y, b = blockIdx.z;
    int tid = threadIdx.x;
    {
        int x = tid >> 2, p = tid & 3;
        float off0 = g_off[((((size_t)b * 4) + (head * 2 + 0)) * 64 + y) * 64 + x];
        float off1 = g_off[((((size_t)b * 4) + (head * 2 + 1)) * 64 + y) * 64 + x];
        float av   = g_attn[((((size_t)b * 2) + head) * 64 + y) * 64 + x];
        float s = av * Wp[head * NPTS + p];
        float g0 = (-1.0f + (float)y * (2.0f / 63.0f)) + bpts[p * 2 + 0] + off0;
        float g1 = (-1.0f + (float)x * (2.0f / 63.0f)) + bpts[p * 2 + 1] + off1;
        float gx = (g0 + 1.0f) * 0.5f * 63.0f;
        float gy = (g1 + 1.0f) * 0.5f * 63.0f;
        float x0f = floorf(gx), y0f = floorf(gy);
        float wx1 = gx - x0f, wx0 = 1.0f - wx1;
        float wy1 = gy - y0f, wy0 = 1.0f - wy1;
        int x0 = (int)x0f, y0i = (int)y0f;
        int xs_[2] = {x0, x0 + 1};
        int ys_[2] = {y0i, y0i + 1};
        float wxv[2] = {wx0, wx1};
        float wyv[2] = {wy0, wy1};
#pragma unroll
        for (int ty2 = 0; ty2 < 2; ty2++)
#pragma unroll
            for (int tx2 = 0; tx2 < 2; tx2++) {
                int xi = xs_[tx2], yi = ys_[ty2];
                bool valid = (xi >= 0) && (xi <= 63) && (yi >= 0) && (yi <= 63);
                int t = ty2 * 2 + tx2;
                s_w[x][p * 4 + t]   = valid ? (wxv[tx2] * wyv[ty2] * s) : 0.0f;
                s_idx[x][p * 4 + t] = valid ? ((yi * 64 + xi) * CH) : 0;
            }
    }
    __syncthreads();
    int lane = tid & 31, warp = tid >> 5;
    const __nv_bfloat16* spb = g_spb + (size_t)b * HWP * CH + lane * 8;
    __nv_bfloat16* hvb = g_hvb + (size_t)b * HWP * (HEADS * CH) + head * CH + lane * 8;
#pragma unroll
    for (int xi = 0; xi < 8; xi++) {
        int x = warp * 8 + xi;
        float a0 = 0.f, a1 = 0.f, a2 = 0.f, a3 = 0.f, a4 = 0.f, a5 = 0.f, a6 = 0.f, a7 = 0.f;
#pragma unroll
        for (int t = 0; t < 16; t++) {
            float w = s_w[x][t];
            if (w != 0.0f) {
                uint4 v = *(const uint4*)(spb + s_idx[x][t]);
                a0 += w * __uint_as_float(v.x << 16);
                a1 += w * __uint_as_float(v.x & 0xFFFF0000u);
                a2 += w * __uint_as_float(v.y << 16);
                a3 += w * __uint_as_float(v.y & 0xFFFF0000u);
                a4 += w * __uint_as_float(v.z << 16);
                a5 += w * __uint_as_float(v.z & 0xFFFF0000u);
                a6 += w * __uint_as_float(v.w << 16);
                a7 += w * __uint_as_float(v.w & 0xFFFF0000u);
            }
        }
        __nv_bfloat162 p0 = __floats2bfloat162_rn(a0, a1);
        __nv_bfloat162 p1 = __floats2bfloat162_rn(a2, a3);
        __nv_bfloat162 p2 = __floats2bfloat162_rn(a4, a5);
        __nv_bfloat162 p3 = __floats2bfloat162_rn(a6, a7);
        uint4 o;
        o.x = *(uint32_t*)&p0; o.y = *(uint32_t*)&p1; o.z = *(uint32_t*)&p2; o.w = *(uint32_t*)&p3;
        *(uint4*)(hvb + (size_t)(y * 64 + x) * (HEADS * CH)) = o;
    }
}

// ---------------- fuse 1x1 conv: pipelined bf16 TC GEMM + blend ----------------
#define TILE_BYTES (128 * PADK * 2)
__global__ __launch_bounds__(256) void k_fuse_gemm(const float* __restrict__ Wt,
                                                   const float* __restrict__ bias,
                                                   const float* __restrict__ res,
                                                   float* __restrict__ out) {
    __shared__ __align__(16) char smraw[4 * TILE_BYTES];
    typedef __nv_bfloat16 (*TileP)[PADK];
    TileP Abuf[2] = { (TileP)(smraw),                  (TileP)(smraw + TILE_BYTES) };
    TileP Bbuf[2] = { (TileP)(smraw + 2 * TILE_BYTES), (TileP)(smraw + 3 * TILE_BYTES) };
    float (*Cs)[34] = (float(*)[34])smraw;

    int b  = blockIdx.z;
    int p0 = blockIdx.x * 128, o0 = blockIdx.y * 128;
    const __nv_bfloat16* Ab = g_hvb + (size_t)b * HWP * 512;
    int tid = threadIdx.x, lane = tid & 31, warp = tid >> 5;
    int wm = warp >> 2, wn = warp & 3;
    float acc[4][4][4];
#pragma unroll
    for (int mi = 0; mi < 4; mi++)
#pragma unroll
        for (int ni = 0; ni < 4; ni++)
#pragma unroll
            for (int q = 0; q < 4; q++) acc[mi][ni][q] = 0.0f;

    uint4 sA4[2];
    __nv_bfloat162 sB[8];
#pragma unroll
    for (int j = 0; j < 2; j++) {
        int l = tid + j * 256;
        sA4[j] = *(const uint4*)(Ab + (size_t)(p0 + (l >> 2)) * 512 + (l & 3) * 8);
    }
#pragma unroll
    for (int j = 0; j < 8; j++) {
        int l = tid + j * 256;
        float2 v = *(const float2*)&Wt[(size_t)(o0 + (l >> 4)) * 512 + 2 * (l & 15)];
        sB[j] = __floats2bfloat162_rn(v.x, v.y);
    }
#pragma unroll
    for (int j = 0; j < 2; j++) {
        int l = tid + j * 256;
        *(uint4*)&Abuf[0][l >> 2][(l & 3) * 8] = sA4[j];
    }
#pragma unroll
    for (int j = 0; j < 8; j++) {
        int l = tid + j * 256;
        *(__nv_bfloat162*)&Bbuf[0][l >> 4][2 * (l & 15)] = sB[j];
    }
    __syncthreads();

#pragma unroll
    for (int it = 0; it < 16; it++) {
        int cur = it & 1;
        if (it < 15) {
            int k0 = (it + 1) * 32;
#pragma unroll
            for (int j = 0; j < 2; j++) {
                int l = tid + j * 256;
                sA4[j] = *(const uint4*)(Ab + (size_t)(p0 + (l >> 2)) * 512 + k0 + (l & 3) * 8);
            }
#pragma unroll
            for (int j = 0; j < 8; j++) {
                int l = tid + j * 256;
                float2 v = *(const float2*)&Wt[(size_t)(o0 + (l >> 4)) * 512 + k0 + 2 * (l & 15)];
                sB[j] = __floats2bfloat162_rn(v.x, v.y);
            }
        }
#pragma unroll
        for (int ks = 0; ks < 32; ks += 16) {
            uint32_t af[4][4], bf[4][2];
#pragma unroll
            for (int mi = 0; mi < 4; mi++)
                ldsm_x4(af[mi][0], af[mi][1], af[mi][2], af[mi][3],
                        smem_u32(&Abuf[cur][wm * 64 + mi * 16 + (lane & 15)][ks + (lane >> 4) * 8]));
#pragma unroll
            for (int ni = 0; ni < 4; ni++)
                ldsm_x2(bf[ni][0], bf[ni][1],
                        smem_u32(&Bbuf[cur][wn * 32 + ni * 8 + (lane & 7)][ks + ((lane >> 3) & 1) * 8]));
#pragma unroll
            for (int mi = 0; mi < 4; mi++)
#pragma unroll
                for (int ni = 0; ni < 4; ni++) mma16816(acc[mi][ni], af[mi], bf[ni]);
        }
        if (it < 15) {
#pragma unroll
            for (int j = 0; j < 2; j++) {
                int l = tid + j * 256;
                *(uint4*)&Abuf[cur ^ 1][l >> 2][(l & 3) * 8] = sA4[j];
            }
#pragma unroll
            for (int j = 0; j < 8; j++) {
                int l = tid + j * 256;
                *(__nv_bfloat162*)&Bbuf[cur ^ 1][l >> 4][2 * (l & 15)] = sB[j];
            }
        }
        __syncthreads();
    }
    float al = g_alpha[b];
    for (int j = 0; j < 4; j++) {
        if (wn == j) {
#pragma unroll
            for (int mi = 0; mi < 4; mi++) {
                int m = wm * 64 + mi * 16 + (lane >> 2);
#pragma unroll
                for (int ni = 0; ni < 4; ni++) {
                    int nl = ni * 8 + (lane & 3) * 2;
                    *(float2*)&Cs[m][nl]     = make_float2(acc[mi][ni][0], acc[mi][ni][1]);
                    *(float2*)&Cs[m + 8][nl] = make_float2(acc[mi][ni][2], acc[mi][ni][3]);
                }
            }
        }
        __syncthreads();
        int pix = tid & 127, ob = tid >> 7;
#pragma unroll
        for (int oi = 0; oi < 16; oi++) {
            int ol = ob + oi * 2;
            int o = o0 + j * 32 + ol;
            float v = Cs[pix][ol] + bias[o];
            size_t gi = ((size_t)b * CH + o) * HWP + p0 + pix;
            out[gi] = al * v + (1.0f - al) * res[gi];
        }
        __syncthreads();
    }
}

// ---------------- launch (k_conv_part at index 3 for ncu) ----------------
extern "C" void kernel_launch(void* const* d_in, const int* in_sizes, int n_in,
                              void* d_out, int out_size) {
    const float* res    = (const float*)d_in[0];
    const float* sty    = (const float*)d_in[1];
    const float* temb   = (const float*)d_in[2];
    const float* spw    = (const float*)d_in[3];
    const float* spb    = (const float*)d_in[4];
    const float* offw   = (const float*)d_in[5];
    const float* offb   = (const float*)d_in[6];
    const float* attw   = (const float*)d_in[7];
    const float* attb   = (const float*)d_in[8];
    const float* Wp     = (const float*)d_in[9];
    const float* fw     = (const float*)d_in[10];
    const float* fb     = (const float*)d_in[11];
    const float* tgw    = (const float*)d_in[12];
    const float* tgb    = (const float*)d_in[13];
    const float* bpts   = (const float*)d_in[14];
    float* out = (float*)d_out;

    k_style_gemm<<<dim3(HWP / 128, CH / 128, BATCH), 256>>>(sty, spw, spb);      // 0
    k_gate<<<4, 256>>>(temb, tgw, tgb, 0);                                       // 1
    k_gate<<<4, 256>>>(temb, tgw, tgb, 4);                                       // 2
    k_conv_part<<<dim3(8, CSPLIT, BATCH), 128>>>(res, sty, offw, attw);          // 3 <- ncu slot
    k_conv_reduce<<<(BATCH * 6 * HWP) / 256, 256>>>(offb, attb);                 // 4
    k_sample<<<dim3(64, HEADS, BATCH), 256>>>(Wp, bpts);                         // 5
    k_loss_part<<<128, 256>>>();                                                 // 6
    k_loss_final<<<1, 128>>>(out, out_size);                                     // 7
    k_fuse_gemm<<<dim3(HWP / 128, CH / 128, BATCH), 256>>>(fw, fb, res, out);    // 8
}